// round 1
// baseline (speedup 1.0000x reference)
#include <cuda_runtime.h>

#define D      1024
#define BATCH  64
#define KSPLIT 8
#define LOG2E  1.4426950408889634f
#define LN2    0.6931471805599453f

// ---------------- scratch (no allocations allowed) ----------------
__device__ __align__(16) float g_xl[BATCH * D];          // x * log2(e)
__device__ __align__(16) float g_bl[BATCH * D];          // Bsum * log2(e)
__device__ __align__(16) float g_xs[BATCH * D];          // soft-sorted x
__device__ __align__(16) float g_h1[BATCH * D];
__device__ __align__(16) float g_h2[BATCH * D];
__device__ __align__(16) float g_part[KSPLIT * BATCH * D];

__device__ __forceinline__ float ex2f(float x) {
    float r;
    asm("ex2.approx.ftz.f32 %0, %1;" : "=f"(r) : "f"(x));
    return r;
}

// ---------------- kernel 1: Bsum per row ----------------
// one block per batch row, 1024 threads, row in smem, broadcast reads
__global__ void prep_kernel(const float* __restrict__ x) {
    int row = blockIdx.x;
    int j   = threadIdx.x;
    __shared__ __align__(16) float sx[D];
    float xj = x[row * D + j];
    sx[j] = xj;
    __syncthreads();
    float a0 = 0.f, a1 = 0.f, a2 = 0.f, a3 = 0.f;
    const float4* sx4 = (const float4*)sx;
#pragma unroll 4
    for (int k = 0; k < D / 4; k++) {
        float4 v = sx4[k];
        a0 += fabsf(xj - v.x);
        a1 += fabsf(xj - v.y);
        a2 += fabsf(xj - v.z);
        a3 += fabsf(xj - v.w);
    }
    float bs = (a0 + a1) + (a2 + a3);
    g_xl[row * D + j] = xj * LOG2E;
    g_bl[row * D + j] = bs * LOG2E;
}

// ---------------- kernel 2: row-wise soft-sort ----------------
// thread-per-output-i; two passes over j (max, then exp2-weighted sums).
// logit2 = c_i * xl_j - bl_j  (log2 domain). xs_i = (sum e*xl)/(sum e) * ln2.
__global__ void softsort_kernel() {
    int row = blockIdx.y;
    int i   = blockIdx.x * blockDim.x + threadIdx.x;
    __shared__ __align__(16) float sxl[D];
    __shared__ __align__(16) float sbl[D];
    const float4* gx4 = (const float4*)(g_xl + row * D);
    const float4* gb4 = (const float4*)(g_bl + row * D);
    for (int t = threadIdx.x; t < D / 4; t += blockDim.x) {
        ((float4*)sxl)[t] = gx4[t];
        ((float4*)sbl)[t] = gb4[t];
    }
    __syncthreads();

    float c  = (float)(D - 1 - 2 * i);
    float mx = -3.4e38f;
    const float4* sx4 = (const float4*)sxl;
    const float4* sb4 = (const float4*)sbl;
#pragma unroll 4
    for (int k = 0; k < D / 4; k++) {
        float4 xv = sx4[k];
        float4 bv = sb4[k];
        mx = fmaxf(mx, fmaf(c, xv.x, -bv.x));
        mx = fmaxf(mx, fmaf(c, xv.y, -bv.y));
        mx = fmaxf(mx, fmaf(c, xv.z, -bv.z));
        mx = fmaxf(mx, fmaf(c, xv.w, -bv.w));
    }
    float num = 0.f, den = 0.f;
#pragma unroll 2
    for (int k = 0; k < D / 4; k++) {
        float4 xv = sx4[k];
        float4 bv = sb4[k];
        float e0 = ex2f(fmaf(c, xv.x, -bv.x) - mx);
        float e1 = ex2f(fmaf(c, xv.y, -bv.y) - mx);
        float e2 = ex2f(fmaf(c, xv.z, -bv.z) - mx);
        float e3 = ex2f(fmaf(c, xv.w, -bv.w) - mx);
        den += e0; num = fmaf(e0, xv.x, num);
        den += e1; num = fmaf(e1, xv.y, num);
        den += e2; num = fmaf(e2, xv.z, num);
        den += e3; num = fmaf(e3, xv.w, num);
    }
    g_xs[row * D + i] = (num * LN2) / den;
}

// ---------------- kernel 3: fp32 GEMM partial, split-K ----------------
// C[64,1024] = A[64,1024] @ W^T (W row-major [o][k]).
// grid (16 n-tiles, KSPLIT). block 256 = 16x16, 4x4 microtile.
__global__ void gemm_part_kernel(int layer, const float* __restrict__ W) {
    const float* A = (layer == 0) ? g_xs : g_h1;
    int nt  = blockIdx.x;
    int ks  = blockIdx.y;
    int tid = threadIdx.x;
    int tx  = tid & 15;
    int ty  = tid >> 4;
    __shared__ __align__(16) float As[16][68];
    __shared__ __align__(16) float Ws[16][68];
    float acc[4][4];
#pragma unroll
    for (int i = 0; i < 4; i++)
#pragma unroll
        for (int j = 0; j < 4; j++) acc[i][j] = 0.f;

    int m_ld = tid >> 2;         // 0..63
    int k4   = (tid & 3) << 2;   // 0,4,8,12
    const int kbase0 = ks * (D / KSPLIT);

    for (int kk = 0; kk < D / KSPLIT; kk += 16) {
        int kb   = kbase0 + kk;
        float4 av = *(const float4*)&A[m_ld * D + kb + k4];
        float4 wv = *(const float4*)&W[(nt * 64 + m_ld) * D + kb + k4];
        __syncthreads();
        As[k4 + 0][m_ld] = av.x; As[k4 + 1][m_ld] = av.y;
        As[k4 + 2][m_ld] = av.z; As[k4 + 3][m_ld] = av.w;
        Ws[k4 + 0][m_ld] = wv.x; Ws[k4 + 1][m_ld] = wv.y;
        Ws[k4 + 2][m_ld] = wv.z; Ws[k4 + 3][m_ld] = wv.w;
        __syncthreads();
#pragma unroll
        for (int k = 0; k < 16; k++) {
            float4 a = *(const float4*)&As[k][ty << 2];
            float4 b = *(const float4*)&Ws[k][tx << 2];
            acc[0][0] = fmaf(a.x, b.x, acc[0][0]);
            acc[0][1] = fmaf(a.x, b.y, acc[0][1]);
            acc[0][2] = fmaf(a.x, b.z, acc[0][2]);
            acc[0][3] = fmaf(a.x, b.w, acc[0][3]);
            acc[1][0] = fmaf(a.y, b.x, acc[1][0]);
            acc[1][1] = fmaf(a.y, b.y, acc[1][1]);
            acc[1][2] = fmaf(a.y, b.z, acc[1][2]);
            acc[1][3] = fmaf(a.y, b.w, acc[1][3]);
            acc[2][0] = fmaf(a.z, b.x, acc[2][0]);
            acc[2][1] = fmaf(a.z, b.y, acc[2][1]);
            acc[2][2] = fmaf(a.z, b.z, acc[2][2]);
            acc[2][3] = fmaf(a.z, b.w, acc[2][3]);
            acc[3][0] = fmaf(a.w, b.x, acc[3][0]);
            acc[3][1] = fmaf(a.w, b.y, acc[3][1]);
            acc[3][2] = fmaf(a.w, b.z, acc[3][2]);
            acc[3][3] = fmaf(a.w, b.w, acc[3][3]);
        }
    }
#pragma unroll
    for (int i = 0; i < 4; i++) {
        int m = (ty << 2) + i;
        float4 v = make_float4(acc[i][0], acc[i][1], acc[i][2], acc[i][3]);
        *(float4*)&g_part[(ks * BATCH + m) * D + nt * 64 + (tx << 2)] = v;
    }
}

// ---------------- kernel 4: split-K combine + bias + LeakyReLU ----------------
__global__ void combine_kernel(int layer, const float* __restrict__ bias) {
    float* H = (layer == 0) ? g_h1 : g_h2;
    int idx = blockIdx.x * blockDim.x + threadIdx.x;
    float s = 0.f;
#pragma unroll
    for (int ks = 0; ks < KSPLIT; ks++) s += g_part[ks * BATCH * D + idx];
    s += bias[idx & (D - 1)];
    H[idx] = (s >= 0.f) ? s : 0.01f * s;
}

// ---------------- kernel 5: final 1024 -> 2 head ----------------
__global__ void final_kernel(const float* __restrict__ W3,
                             const float* __restrict__ b3,
                             float* __restrict__ out) {
    int b   = blockIdx.x;
    int tid = threadIdx.x;         // 256
    int c   = tid >> 7;            // 0 or 1
    int j0  = tid & 127;
    float acc = 0.f;
#pragma unroll
    for (int t = 0; t < 8; t++) {
        int j = j0 + (t << 7);
        acc = fmaf(g_h2[b * D + j], W3[c * D + j], acc);
    }
    __shared__ float red[8];
#pragma unroll
    for (int off = 16; off; off >>= 1)
        acc += __shfl_down_sync(0xffffffffu, acc, off);
    if ((tid & 31) == 0) red[tid >> 5] = acc;
    __syncthreads();
    if (tid < 2) {
        float s = (red[tid * 4] + red[tid * 4 + 1]) +
                  (red[tid * 4 + 2] + red[tid * 4 + 3]);
        out[b * 2 + tid] = s + b3[tid];
    }
}

extern "C" void kernel_launch(void* const* d_in, const int* in_sizes, int n_in,
                              void* d_out, int out_size) {
    const float* x  = (const float*)d_in[0];
    const float* W1 = (const float*)d_in[1];
    const float* b1 = (const float*)d_in[2];
    const float* W2 = (const float*)d_in[3];
    const float* b2 = (const float*)d_in[4];
    const float* W3 = (const float*)d_in[5];
    const float* b3 = (const float*)d_in[6];
    float* out = (float*)d_out;
    (void)in_sizes; (void)n_in; (void)out_size;

    prep_kernel<<<BATCH, D>>>(x);
    softsort_kernel<<<dim3(D / 256, BATCH), 256>>>();
    gemm_part_kernel<<<dim3(D / 64, KSPLIT), 256>>>(0, W1);
    combine_kernel<<<BATCH * D / 256, 256>>>(0, b1);
    gemm_part_kernel<<<dim3(D / 64, KSPLIT), 256>>>(1, W2);
    combine_kernel<<<BATCH * D / 256, 256>>>(1, b2);
    final_kernel<<<BATCH, 256>>>(W3, b3, out);
}

// round 2
// speedup vs baseline: 1.4557x; 1.4557x over previous
#include <cuda_runtime.h>

#define D      1024
#define BATCH  64
#define KSPLIT 8
#define LOG2E  1.4426950408889634f
#define LN2    0.6931471805599453f

// ---------------- scratch (no allocations allowed) ----------------
__device__ __align__(16) float g_xl[BATCH * D];          // sorted x * log2(e)
__device__ __align__(16) float g_bl[BATCH * D];          // Bsum (sorted order) * log2(e)
__device__ __align__(16) float g_xs[BATCH * D];          // soft-sorted x
__device__ __align__(16) float g_h1[BATCH * D];
__device__ __align__(16) float g_h2[BATCH * D];
__device__ __align__(16) float g_part[KSPLIT * BATCH * D];

__device__ __forceinline__ float ex2f(float x) {
    float r;
    asm("ex2.approx.ftz.f32 %0, %1;" : "=f"(r) : "f"(x));
    return r;
}

// ---------------- kernel 1: per-row bitonic sort + prefix-sum Bsum ----------------
// Bsum_r = (2r - D)*v_r + S - 2*P_{r-1}  (ascending sorted, P inclusive prefix)
__global__ void __launch_bounds__(D) sort_kernel(const float* __restrict__ x) {
    int row = blockIdx.x;
    int tid = threadIdx.x;
    __shared__ __align__(16) float sv[D];
    __shared__ float wsum[32];

    sv[tid] = x[row * D + tid];
    __syncthreads();

    for (int k = 2; k <= D; k <<= 1) {
        for (int j = k >> 1; j > 0; j >>= 1) {
            int ixj = tid ^ j;
            if (ixj > tid) {
                float a = sv[tid], b = sv[ixj];
                bool up = ((tid & k) == 0);
                if ((a > b) == up) { sv[tid] = b; sv[ixj] = a; }
            }
            __syncthreads();
        }
    }

    float v = sv[tid];
    int lane = tid & 31, wid = tid >> 5;
    // warp inclusive scan
    float p = v;
#pragma unroll
    for (int off = 1; off < 32; off <<= 1) {
        float n = __shfl_up_sync(0xffffffffu, p, off);
        if (lane >= off) p += n;
    }
    if (lane == 31) wsum[wid] = p;
    __syncthreads();
    if (wid == 0) {
        float w = wsum[lane];
#pragma unroll
        for (int off = 1; off < 32; off <<= 1) {
            float n = __shfl_up_sync(0xffffffffu, w, off);
            if (lane >= off) w += n;
        }
        wsum[lane] = w;
    }
    __syncthreads();
    float S    = wsum[31];
    float pinc = p + (wid ? wsum[wid - 1] : 0.f);
    float bs   = (float)(2 * tid - D) * v + S - 2.f * (pinc - v);
    g_xl[row * D + tid] = v * LOG2E;
    g_bl[row * D + tid] = bs * LOG2E;
}

// ---------------- kernel 2: windowed soft-sort ----------------
// logits over sorted ranks are unimodal; exact max at rank rm = D-1-i.
// Early-exit when term < 2^-30 of max (monotone decay => exact truncation).
__global__ void __launch_bounds__(256) softsort_kernel() {
    int row = blockIdx.y;
    int i   = blockIdx.x * blockDim.x + threadIdx.x;
    __shared__ __align__(16) float sxl[D];
    __shared__ __align__(16) float sbl[D];
    ((float4*)sxl)[threadIdx.x] = ((const float4*)(g_xl + row * D))[threadIdx.x];
    ((float4*)sbl)[threadIdx.x] = ((const float4*)(g_bl + row * D))[threadIdx.x];
    __syncthreads();

    float c  = (float)(D - 1 - 2 * i);
    int   rm = D - 1 - i;
    float mx = fmaf(c, sxl[rm], -sbl[rm]);
    float num = sxl[rm], den = 1.f;
    const float T = 30.f;

    for (int r = rm - 1; r >= 0; --r) {
        float t = fmaf(c, sxl[r], -sbl[r]) - mx;
        if (t < -T) break;
        float e = ex2f(t);
        den += e; num = fmaf(e, sxl[r], num);
    }
    for (int r = rm + 1; r < D; ++r) {
        float t = fmaf(c, sxl[r], -sbl[r]) - mx;
        if (t < -T) break;
        float e = ex2f(t);
        den += e; num = fmaf(e, sxl[r], num);
    }
    g_xs[row * D + i] = num * LN2 / den;
}

// ---------------- kernel 3: fp32 GEMM partial, split-K ----------------
__global__ void __launch_bounds__(256) gemm_part_kernel(int layer, const float* __restrict__ W) {
    const float* A = (layer == 0) ? g_xs : g_h1;
    int nt  = blockIdx.x;
    int ks  = blockIdx.y;
    int tid = threadIdx.x;
    int tx  = tid & 15;
    int ty  = tid >> 4;
    __shared__ __align__(16) float As[16][68];
    __shared__ __align__(16) float Ws[16][68];
    float acc[4][4];
#pragma unroll
    for (int i = 0; i < 4; i++)
#pragma unroll
        for (int j = 0; j < 4; j++) acc[i][j] = 0.f;

    int m_ld = tid >> 2;
    int k4   = (tid & 3) << 2;
    const int kbase0 = ks * (D / KSPLIT);

    for (int kk = 0; kk < D / KSPLIT; kk += 16) {
        int kb = kbase0 + kk;
        float4 av = *(const float4*)&A[m_ld * D + kb + k4];
        float4 wv = *(const float4*)&W[(nt * 64 + m_ld) * D + kb + k4];
        __syncthreads();
        As[k4 + 0][m_ld] = av.x; As[k4 + 1][m_ld] = av.y;
        As[k4 + 2][m_ld] = av.z; As[k4 + 3][m_ld] = av.w;
        Ws[k4 + 0][m_ld] = wv.x; Ws[k4 + 1][m_ld] = wv.y;
        Ws[k4 + 2][m_ld] = wv.z; Ws[k4 + 3][m_ld] = wv.w;
        __syncthreads();
#pragma unroll
        for (int k = 0; k < 16; k++) {
            float4 a = *(const float4*)&As[k][ty << 2];
            float4 b = *(const float4*)&Ws[k][tx << 2];
            acc[0][0] = fmaf(a.x, b.x, acc[0][0]);
            acc[0][1] = fmaf(a.x, b.y, acc[0][1]);
            acc[0][2] = fmaf(a.x, b.z, acc[0][2]);
            acc[0][3] = fmaf(a.x, b.w, acc[0][3]);
            acc[1][0] = fmaf(a.y, b.x, acc[1][0]);
            acc[1][1] = fmaf(a.y, b.y, acc[1][1]);
            acc[1][2] = fmaf(a.y, b.z, acc[1][2]);
            acc[1][3] = fmaf(a.y, b.w, acc[1][3]);
            acc[2][0] = fmaf(a.z, b.x, acc[2][0]);
            acc[2][1] = fmaf(a.z, b.y, acc[2][1]);
            acc[2][2] = fmaf(a.z, b.z, acc[2][2]);
            acc[2][3] = fmaf(a.z, b.w, acc[2][3]);
            acc[3][0] = fmaf(a.w, b.x, acc[3][0]);
            acc[3][1] = fmaf(a.w, b.y, acc[3][1]);
            acc[3][2] = fmaf(a.w, b.z, acc[3][2]);
            acc[3][3] = fmaf(a.w, b.w, acc[3][3]);
        }
    }
#pragma unroll
    for (int i = 0; i < 4; i++) {
        int m = (ty << 2) + i;
        float4 v = make_float4(acc[i][0], acc[i][1], acc[i][2], acc[i][3]);
        *(float4*)&g_part[(ks * BATCH + m) * D + nt * 64 + (tx << 2)] = v;
    }
}

// ---------------- kernel 4: split-K combine + bias + LeakyReLU (float4) ----------------
__global__ void __launch_bounds__(256) combine_kernel(int layer, const float* __restrict__ bias) {
    float* H = (layer == 0) ? g_h1 : g_h2;
    int idx4 = blockIdx.x * blockDim.x + threadIdx.x;      // 16384 float4s
    float4 s = ((const float4*)g_part)[idx4];
#pragma unroll
    for (int ks = 1; ks < KSPLIT; ks++) {
        float4 v = ((const float4*)g_part)[ks * (BATCH * D / 4) + idx4];
        s.x += v.x; s.y += v.y; s.z += v.z; s.w += v.w;
    }
    float4 bv = ((const float4*)bias)[idx4 & (D / 4 - 1)];
    s.x += bv.x; s.y += bv.y; s.z += bv.z; s.w += bv.w;
    s.x = (s.x >= 0.f) ? s.x : 0.01f * s.x;
    s.y = (s.y >= 0.f) ? s.y : 0.01f * s.y;
    s.z = (s.z >= 0.f) ? s.z : 0.01f * s.z;
    s.w = (s.w >= 0.f) ? s.w : 0.01f * s.w;
    ((float4*)H)[idx4] = s;
}

// ---------------- kernel 5: final 1024 -> 2 head ----------------
__global__ void __launch_bounds__(256) final_kernel(const float* __restrict__ W3,
                                                    const float* __restrict__ b3,
                                                    float* __restrict__ out) {
    int b   = blockIdx.x;
    int tid = threadIdx.x;
    int c   = tid >> 7;
    int j0  = tid & 127;
    float acc = 0.f;
#pragma unroll
    for (int t = 0; t < 8; t++) {
        int j = j0 + (t << 7);
        acc = fmaf(g_h2[b * D + j], W3[c * D + j], acc);
    }
    __shared__ float red[8];
#pragma unroll
    for (int off = 16; off; off >>= 1)
        acc += __shfl_down_sync(0xffffffffu, acc, off);
    if ((tid & 31) == 0) red[tid >> 5] = acc;
    __syncthreads();
    if (tid < 2) {
        float s = (red[tid * 4] + red[tid * 4 + 1]) +
                  (red[tid * 4 + 2] + red[tid * 4 + 3]);
        out[b * 2 + tid] = s + b3[tid];
    }
}

extern "C" void kernel_launch(void* const* d_in, const int* in_sizes, int n_in,
                              void* d_out, int out_size) {
    const float* x  = (const float*)d_in[0];
    const float* W1 = (const float*)d_in[1];
    const float* b1 = (const float*)d_in[2];
    const float* W2 = (const float*)d_in[3];
    const float* b2 = (const float*)d_in[4];
    const float* W3 = (const float*)d_in[5];
    const float* b3 = (const float*)d_in[6];
    float* out = (float*)d_out;
    (void)in_sizes; (void)n_in; (void)out_size;

    sort_kernel<<<BATCH, D>>>(x);
    softsort_kernel<<<dim3(D / 256, BATCH), 256>>>();
    gemm_part_kernel<<<dim3(D / 64, KSPLIT), 256>>>(0, W1);
    combine_kernel<<<BATCH * D / 1024, 256>>>(0, b1);
    gemm_part_kernel<<<dim3(D / 64, KSPLIT), 256>>>(1, W2);
    combine_kernel<<<BATCH * D / 1024, 256>>>(1, b2);
    final_kernel<<<BATCH, 256>>>(W3, b3, out);
}

// round 3
// speedup vs baseline: 1.6061x; 1.1033x over previous
#include <cuda_runtime.h>

#define D      1024
#define BATCH  64
#define KSPLIT 8
#define NTILES (D / 64)
#define LOG2E  1.4426950408889634f
#define LN2    0.6931471805599453f

// ---------------- scratch (no allocations allowed) ----------------
__device__ __align__(16) float g_xl[BATCH * D];          // sorted x * log2(e)
__device__ __align__(16) float g_bl[BATCH * D];          // Bsum (sorted order) * log2(e)
__device__ __align__(16) float g_xs[BATCH * D];          // soft-sorted x
__device__ __align__(16) float g_h1[BATCH * D];
__device__ __align__(16) float g_h2[BATCH * D];
__device__ __align__(16) float g_part[KSPLIT * BATCH * D];
__device__ unsigned g_cnt[2][NTILES];                    // zero-init; reset by last block

__device__ __forceinline__ float ex2f(float x) {
    float r;
    asm("ex2.approx.ftz.f32 %0, %1;" : "=f"(r) : "f"(x));
    return r;
}

// ---------------- kernel 1: per-row bitonic sort + prefix-sum Bsum ----------------
// Bsum_r = (2r - D)*v_r + S - 2*P_{r-1}  (ascending sorted, P inclusive prefix)
__global__ void __launch_bounds__(D) sort_kernel(const float* __restrict__ x) {
    int row = blockIdx.x;
    int tid = threadIdx.x;
    __shared__ __align__(16) float sv[D];
    __shared__ float wsum[32];

    sv[tid] = x[row * D + tid];
    __syncthreads();

    for (int k = 2; k <= D; k <<= 1) {
        for (int j = k >> 1; j > 0; j >>= 1) {
            int ixj = tid ^ j;
            if (ixj > tid) {
                float a = sv[tid], b = sv[ixj];
                bool up = ((tid & k) == 0);
                if ((a > b) == up) { sv[tid] = b; sv[ixj] = a; }
            }
            __syncthreads();
        }
    }

    float v = sv[tid];
    int lane = tid & 31, wid = tid >> 5;
    float p = v;
#pragma unroll
    for (int off = 1; off < 32; off <<= 1) {
        float n = __shfl_up_sync(0xffffffffu, p, off);
        if (lane >= off) p += n;
    }
    if (lane == 31) wsum[wid] = p;
    __syncthreads();
    if (wid == 0) {
        float w = wsum[lane];
#pragma unroll
        for (int off = 1; off < 32; off <<= 1) {
            float n = __shfl_up_sync(0xffffffffu, w, off);
            if (lane >= off) w += n;
        }
        wsum[lane] = w;
    }
    __syncthreads();
    float S    = wsum[31];
    float pinc = p + (wid ? wsum[wid - 1] : 0.f);
    float bs   = (float)(2 * tid - D) * v + S - 2.f * (pinc - v);
    g_xl[row * D + tid] = v * LOG2E;
    g_bl[row * D + tid] = bs * LOG2E;
}

// ---------------- kernel 2: windowed soft-sort, unroll-4 ----------------
__global__ void __launch_bounds__(256) softsort_kernel() {
    int row = blockIdx.y;
    int i   = blockIdx.x * blockDim.x + threadIdx.x;
    __shared__ __align__(16) float sxl[D];
    __shared__ __align__(16) float sbl[D];
    ((float4*)sxl)[threadIdx.x] = ((const float4*)(g_xl + row * D))[threadIdx.x];
    ((float4*)sbl)[threadIdx.x] = ((const float4*)(g_bl + row * D))[threadIdx.x];
    __syncthreads();

    float c  = (float)(D - 1 - 2 * i);
    int   rm = D - 1 - i;
    float mx = fmaf(c, sxl[rm], -sbl[rm]);
    float num = sxl[rm], den = 1.f;
    const float T = 22.f;

    // downward scan (monotone decreasing away from peak)
    {
        int r = rm - 1;
        for (; r >= 3; r -= 4) {
            float t0 = fmaf(c, sxl[r],     -sbl[r])     - mx;
            float t1 = fmaf(c, sxl[r - 1], -sbl[r - 1]) - mx;
            float t2 = fmaf(c, sxl[r - 2], -sbl[r - 2]) - mx;
            float t3 = fmaf(c, sxl[r - 3], -sbl[r - 3]) - mx;
            float e0 = ex2f(t0), e1 = ex2f(t1), e2 = ex2f(t2), e3 = ex2f(t3);
            den += e0; num = fmaf(e0, sxl[r],     num);
            den += e1; num = fmaf(e1, sxl[r - 1], num);
            den += e2; num = fmaf(e2, sxl[r - 2], num);
            den += e3; num = fmaf(e3, sxl[r - 3], num);
            if (t3 < -T) { r = -1; break; }
        }
        for (; r >= 0; --r) {
            float t = fmaf(c, sxl[r], -sbl[r]) - mx;
            if (t < -T) break;
            float e = ex2f(t);
            den += e; num = fmaf(e, sxl[r], num);
        }
    }
    // upward scan
    {
        int r = rm + 1;
        for (; r < D - 3; r += 4) {
            float t0 = fmaf(c, sxl[r],     -sbl[r])     - mx;
            float t1 = fmaf(c, sxl[r + 1], -sbl[r + 1]) - mx;
            float t2 = fmaf(c, sxl[r + 2], -sbl[r + 2]) - mx;
            float t3 = fmaf(c, sxl[r + 3], -sbl[r + 3]) - mx;
            float e0 = ex2f(t0), e1 = ex2f(t1), e2 = ex2f(t2), e3 = ex2f(t3);
            den += e0; num = fmaf(e0, sxl[r],     num);
            den += e1; num = fmaf(e1, sxl[r + 1], num);
            den += e2; num = fmaf(e2, sxl[r + 2], num);
            den += e3; num = fmaf(e3, sxl[r + 3], num);
            if (t3 < -T) { r = D; break; }
        }
        for (; r < D; ++r) {
            float t = fmaf(c, sxl[r], -sbl[r]) - mx;
            if (t < -T) break;
            float e = ex2f(t);
            den += e; num = fmaf(e, sxl[r], num);
        }
    }
    g_xs[row * D + i] = num * LN2 / den;
}

// ---------------- kernel 3: split-K GEMM + fused last-block combine ----------------
// C[64,1024] = A[64,1024] @ W^T. grid (NTILES, KSPLIT), block 256.
// Last-arriving block per n-tile sums partials in fixed ks order (deterministic),
// adds bias + LeakyReLU, writes H, resets the counter for graph replay.
__global__ void __launch_bounds__(256) gemm_fused_kernel(int layer,
                                                         const float* __restrict__ W,
                                                         const float* __restrict__ bias) {
    const float* A = (layer == 0) ? g_xs : g_h1;
    float*       H = (layer == 0) ? g_h1 : g_h2;
    int nt  = blockIdx.x;
    int ks  = blockIdx.y;
    int tid = threadIdx.x;
    int tx  = tid & 15;
    int ty  = tid >> 4;
    __shared__ __align__(16) float As[16][68];
    __shared__ __align__(16) float Ws[16][68];
    __shared__ int s_last;
    float acc[4][4];
#pragma unroll
    for (int i = 0; i < 4; i++)
#pragma unroll
        for (int j = 0; j < 4; j++) acc[i][j] = 0.f;

    int m_ld = tid >> 2;
    int k4   = (tid & 3) << 2;
    const int kbase0 = ks * (D / KSPLIT);

    for (int kk = 0; kk < D / KSPLIT; kk += 16) {
        int kb = kbase0 + kk;
        float4 av = *(const float4*)&A[m_ld * D + kb + k4];
        float4 wv = *(const float4*)&W[(nt * 64 + m_ld) * D + kb + k4];
        __syncthreads();
        As[k4 + 0][m_ld] = av.x; As[k4 + 1][m_ld] = av.y;
        As[k4 + 2][m_ld] = av.z; As[k4 + 3][m_ld] = av.w;
        Ws[k4 + 0][m_ld] = wv.x; Ws[k4 + 1][m_ld] = wv.y;
        Ws[k4 + 2][m_ld] = wv.z; Ws[k4 + 3][m_ld] = wv.w;
        __syncthreads();
#pragma unroll
        for (int k = 0; k < 16; k++) {
            float4 a = *(const float4*)&As[k][ty << 2];
            float4 b = *(const float4*)&Ws[k][tx << 2];
            acc[0][0] = fmaf(a.x, b.x, acc[0][0]);
            acc[0][1] = fmaf(a.x, b.y, acc[0][1]);
            acc[0][2] = fmaf(a.x, b.z, acc[0][2]);
            acc[0][3] = fmaf(a.x, b.w, acc[0][3]);
            acc[1][0] = fmaf(a.y, b.x, acc[1][0]);
            acc[1][1] = fmaf(a.y, b.y, acc[1][1]);
            acc[1][2] = fmaf(a.y, b.z, acc[1][2]);
            acc[1][3] = fmaf(a.y, b.w, acc[1][3]);
            acc[2][0] = fmaf(a.z, b.x, acc[2][0]);
            acc[2][1] = fmaf(a.z, b.y, acc[2][1]);
            acc[2][2] = fmaf(a.z, b.z, acc[2][2]);
            acc[2][3] = fmaf(a.z, b.w, acc[2][3]);
            acc[3][0] = fmaf(a.w, b.x, acc[3][0]);
            acc[3][1] = fmaf(a.w, b.y, acc[3][1]);
            acc[3][2] = fmaf(a.w, b.z, acc[3][2]);
            acc[3][3] = fmaf(a.w, b.w, acc[3][3]);
        }
    }
#pragma unroll
    for (int i = 0; i < 4; i++) {
        int m = (ty << 2) + i;
        float4 v = make_float4(acc[i][0], acc[i][1], acc[i][2], acc[i][3]);
        *(float4*)&g_part[(ks * BATCH + m) * D + nt * 64 + (tx << 2)] = v;
    }

    // ---- election: last block for this n-tile does the combine ----
    __syncthreads();
    __threadfence();
    if (tid == 0) {
        unsigned old = atomicAdd(&g_cnt[layer][nt], 1u);
        s_last = (old == KSPLIT - 1);
        if (s_last) g_cnt[layer][nt] = 0;   // reset for next graph replay
    }
    __syncthreads();
    if (!s_last) return;
    __threadfence();

    // combine 64 rows x 16 float4-cols of this tile: 1024 float4s, 4 per thread
#pragma unroll
    for (int t = 0; t < 4; t++) {
        int idx = t * 256 + tid;           // 0..1023
        int m   = idx >> 4;                // row
        int c4  = idx & 15;                // float4 col within tile
        int f4  = (m * (D / 4)) + nt * 16 + c4;
        float4 s = ((const float4*)g_part)[(0 * BATCH + m) * (D / 4) + nt * 16 + c4];
#pragma unroll
        for (int k = 1; k < KSPLIT; k++) {
            float4 v = ((const float4*)g_part)[(k * BATCH + m) * (D / 4) + nt * 16 + c4];
            s.x += v.x; s.y += v.y; s.z += v.z; s.w += v.w;
        }
        float4 bv = ((const float4*)bias)[nt * 16 + c4];
        s.x += bv.x; s.y += bv.y; s.z += bv.z; s.w += bv.w;
        s.x = (s.x >= 0.f) ? s.x : 0.01f * s.x;
        s.y = (s.y >= 0.f) ? s.y : 0.01f * s.y;
        s.z = (s.z >= 0.f) ? s.z : 0.01f * s.z;
        s.w = (s.w >= 0.f) ? s.w : 0.01f * s.w;
        ((float4*)H)[f4] = s;
    }
}

// ---------------- kernel 4: final 1024 -> 2 head ----------------
__global__ void __launch_bounds__(256) final_kernel(const float* __restrict__ W3,
                                                    const float* __restrict__ b3,
                                                    float* __restrict__ out) {
    int b   = blockIdx.x;
    int tid = threadIdx.x;
    int c   = tid >> 7;
    int j0  = tid & 127;
    float acc = 0.f;
#pragma unroll
    for (int t = 0; t < 8; t++) {
        int j = j0 + (t << 7);
        acc = fmaf(g_h2[b * D + j], W3[c * D + j], acc);
    }
    __shared__ float red[8];
#pragma unroll
    for (int off = 16; off; off >>= 1)
        acc += __shfl_down_sync(0xffffffffu, acc, off);
    if ((tid & 31) == 0) red[tid >> 5] = acc;
    __syncthreads();
    if (tid < 2) {
        float s = (red[tid * 4] + red[tid * 4 + 1]) +
                  (red[tid * 4 + 2] + red[tid * 4 + 3]);
        out[b * 2 + tid] = s + b3[tid];
    }
}

extern "C" void kernel_launch(void* const* d_in, const int* in_sizes, int n_in,
                              void* d_out, int out_size) {
    const float* x  = (const float*)d_in[0];
    const float* W1 = (const float*)d_in[1];
    const float* b1 = (const float*)d_in[2];
    const float* W2 = (const float*)d_in[3];
    const float* b2 = (const float*)d_in[4];
    const float* W3 = (const float*)d_in[5];
    const float* b3 = (const float*)d_in[6];
    float* out = (float*)d_out;
    (void)in_sizes; (void)n_in; (void)out_size;

    sort_kernel<<<BATCH, D>>>(x);
    softsort_kernel<<<dim3(D / 256, BATCH), 256>>>();
    gemm_fused_kernel<<<dim3(NTILES, KSPLIT), 256>>>(0, W1, b1);
    gemm_fused_kernel<<<dim3(NTILES, KSPLIT), 256>>>(1, W2, b2);
    final_kernel<<<BATCH, 256>>>(W3, b3, out);
}